// round 4
// baseline (speedup 1.0000x reference)
#include <cuda_runtime.h>
#include <cuda_bf16.h>

#define B_  64
#define N_  16
#define T_  128
#define I_  256
#define H_  256
#define G3  768    // 3*H
#define NCTA 128   // persistent-kernel CTA count (8 jc x 16 n)
#define WR  260    // padded ws row length (floats): conflict-free float4 reads

// Scratch: precomputed input projection IH[n][t][b][g] (bih folded in), 402 MB BSS.
__device__ float g_IH[(size_t)N_ * T_ * B_ * G3];
// Double-buffered hidden state h[2][n][b][k].
__device__ float g_h[2 * N_ * B_ * H_];
// Software grid barrier state (reset every launch/replay by zero_kernel).
__device__ int g_bar_count;
__device__ volatile int g_bar_gen;

// ---------------------------------------------------------------------------
// Zero hidden state + barrier state.
// ---------------------------------------------------------------------------
__global__ void zero_kernel() {
    int i = blockIdx.x * blockDim.x + threadIdx.x;
    if (i < 2 * N_ * B_ * H_) g_h[i] = 0.0f;
    if (i == 0) { g_bar_count = 0; g_bar_gen = 0; }
}

// ---------------------------------------------------------------------------
// Phase 1: IH[n][t][b][g] = bih[n][g] + sum_i x[b][n][t][i] * wih[n][g][i]
// Tiled fp32 SGEMM, 64x64 tile, k-tile 32, 256 threads, 4x4 microtile.
// ---------------------------------------------------------------------------
__global__ void ih_gemm_kernel(const float* __restrict__ x,
                               const float* __restrict__ wih,
                               const float* __restrict__ bih) {
    __shared__ float As[32 * 68];   // [k][m]
    __shared__ float Bs[32 * 68];   // [k][g]

    const int n   = blockIdx.z;
    const int by  = blockIdx.y;     // m tile over B*T = 8192 (128 tiles)
    const int bx  = blockIdx.x;     // g tile over 768 (12 tiles)
    const int tid = threadIdx.x;
    const int tx  = tid & 15;
    const int ty  = tid >> 4;

    float acc[4][4];
#pragma unroll
    for (int i = 0; i < 4; i++)
#pragma unroll
        for (int j = 0; j < 4; j++) acc[i][j] = 0.0f;

    for (int k0 = 0; k0 < I_; k0 += 32) {
#pragma unroll
        for (int l = 0; l < 2; l++) {
            int item = tid + (l << 8);
            int r = item >> 3;          // row within tile (0..63)
            int q = item & 7;           // float4 index
            int c0 = q << 2;

            int m = (by << 6) + r;
            int b = m >> 7, t = m & 127;
            float4 av = *(const float4*)(x + (((size_t)(b * N_ + n) * T_ + t) * I_) + k0 + c0);
            As[(c0 + 0) * 68 + r] = av.x;
            As[(c0 + 1) * 68 + r] = av.y;
            As[(c0 + 2) * 68 + r] = av.z;
            As[(c0 + 3) * 68 + r] = av.w;

            int g = (bx << 6) + r;
            float4 wv = *(const float4*)(wih + ((size_t)(n * G3 + g) * I_) + k0 + c0);
            Bs[(c0 + 0) * 68 + r] = wv.x;
            Bs[(c0 + 1) * 68 + r] = wv.y;
            Bs[(c0 + 2) * 68 + r] = wv.z;
            Bs[(c0 + 3) * 68 + r] = wv.w;
        }
        __syncthreads();

#pragma unroll
        for (int k = 0; k < 32; k++) {
            float4 a4 = *(const float4*)(As + k * 68 + (ty << 2));
            float4 b4 = *(const float4*)(Bs + k * 68 + (tx << 2));
            float av[4] = {a4.x, a4.y, a4.z, a4.w};
            float bv[4] = {b4.x, b4.y, b4.z, b4.w};
#pragma unroll
            for (int i = 0; i < 4; i++)
#pragma unroll
                for (int j = 0; j < 4; j++)
                    acc[i][j] = fmaf(av[i], bv[j], acc[i][j]);
        }
        __syncthreads();
    }

    const int g0 = (bx << 6) + (tx << 2);
    float4 bias = *(const float4*)(bih + n * G3 + g0);
#pragma unroll
    for (int i = 0; i < 4; i++) {
        int m = (by << 6) + (ty << 2) + i;
        int b = m >> 7, t = m & 127;
        float4 o;
        o.x = acc[i][0] + bias.x;
        o.y = acc[i][1] + bias.y;
        o.z = acc[i][2] + bias.z;
        o.w = acc[i][3] + bias.w;
        *(float4*)(g_IH + (((size_t)(n * T_ + t) * B_ + b) * G3) + g0) = o;
    }
}

// ---------------------------------------------------------------------------
// Phase 2: ONE persistent kernel, all 128 timesteps, software grid barrier.
// Grid (jc=8, n=16) = 128 CTAs, 256 threads, 1 CTA/SM (165 KB smem) -> all
// co-resident in wave 1, so the spin barrier cannot deadlock.
// Whh slice [3][32][256] lives in smem for the whole kernel.
// ---------------------------------------------------------------------------
__global__ void __launch_bounds__(256, 1)
gru_persist_kernel(const float* __restrict__ whh,
                   const float* __restrict__ bhh,
                   float* __restrict__ out) {
    extern __shared__ float sm[];
    float* hs = sm;                 // [64][256] staged h_prev (16384 floats)
    float* ws = sm + B_ * H_;       // [3*32][WR] weights     (24960 floats)

    const int n    = blockIdx.y;
    const int jc   = blockIdx.x;
    const int tid  = threadIdx.x;
    const int lane = tid & 31;
    const int wrp  = tid >> 5;      // b-group 0..7
    const int j    = (jc << 5) + lane;

    // Load Whh slice once: 96 rows (3 gates x 32 j) x 256 k.
    for (int it = tid; it < 96 * 64; it += 256) {
        int row  = it >> 6;         // 0..95
        int q    = it & 63;         // float4 index in k
        int gate = row >> 5;
        int jl   = row & 31;
        float4 wv = *(const float4*)(whh +
            ((size_t)(n * G3 + gate * H_ + (jc << 5) + jl)) * H_ + (q << 2));
        float* d = ws + (size_t)row * WR + (q << 2);
        d[0] = wv.x; d[1] = wv.y; d[2] = wv.z; d[3] = wv.w;
    }
    const float bhr = bhh[n * G3 + j];
    const float bhz = bhh[n * G3 + H_ + j];
    const float bhn = bhh[n * G3 + 2 * H_ + j];
    __syncthreads();

    const float* wrow_r = ws + (0 * 32 + lane) * WR;
    const float* wrow_z = ws + (1 * 32 + lane) * WR;
    const float* wrow_n = ws + (2 * 32 + lane) * WR;

    for (int t = 0; t < T_; t++) {
        // Stage h_prev for this n (L2-coherent loads: bypass stale L1).
        const float* hsrc = g_h + (t & 1) * (N_ * B_ * H_) + n * (B_ * H_);
        for (int i = tid; i < (B_ * H_) / 4; i += 256)
            ((float4*)hs)[i] = __ldcg(((const float4*)hsrc) + i);
        __syncthreads();

        float accr[8], accz[8], accn[8];
#pragma unroll
        for (int i = 0; i < 8; i++) { accr[i] = 0.f; accz[i] = 0.f; accn[i] = 0.f; }

        const float* hbase = hs + (wrp << 3) * H_;
#pragma unroll 4
        for (int kq = 0; kq < H_; kq += 4) {
            float4 wr4 = *(const float4*)(wrow_r + kq);
            float4 wz4 = *(const float4*)(wrow_z + kq);
            float4 wn4 = *(const float4*)(wrow_n + kq);
#pragma unroll
            for (int i = 0; i < 8; i++) {
                float4 hv = *(const float4*)(hbase + i * H_ + kq);
                accr[i] = fmaf(hv.x, wr4.x, accr[i]);
                accr[i] = fmaf(hv.y, wr4.y, accr[i]);
                accr[i] = fmaf(hv.z, wr4.z, accr[i]);
                accr[i] = fmaf(hv.w, wr4.w, accr[i]);
                accz[i] = fmaf(hv.x, wz4.x, accz[i]);
                accz[i] = fmaf(hv.y, wz4.y, accz[i]);
                accz[i] = fmaf(hv.z, wz4.z, accz[i]);
                accz[i] = fmaf(hv.w, wz4.w, accz[i]);
                accn[i] = fmaf(hv.x, wn4.x, accn[i]);
                accn[i] = fmaf(hv.y, wn4.y, accn[i]);
                accn[i] = fmaf(hv.z, wn4.z, accn[i]);
                accn[i] = fmaf(hv.w, wn4.w, accn[i]);
            }
        }

        // Fused gate epilogue.
        const float* ihb = g_IH + ((size_t)(n * T_ + t) * B_) * G3;
        float* hdst = g_h + ((t + 1) & 1) * (N_ * B_ * H_) + n * (B_ * H_);
#pragma unroll
        for (int i = 0; i < 8; i++) {
            int b = (wrp << 3) + i;
            float ihr = ihb[(size_t)b * G3 + j];
            float ihz = ihb[(size_t)b * G3 + H_ + j];
            float ihn = ihb[(size_t)b * G3 + 2 * H_ + j];
            float hr = accr[i] + bhr;
            float hz = accz[i] + bhz;
            float hn = accn[i] + bhn;
            float rg = 1.0f / (1.0f + __expf(-(ihr + hr)));
            float zg = 1.0f / (1.0f + __expf(-(ihz + hz)));
            float ng = tanhf(ihn + rg * hn);
            float hp = hs[b * H_ + j];
            float hnew = (1.0f - zg) * ng + zg * hp;
            hdst[b * H_ + j] = hnew;
            out[((size_t)(b * N_ + n) * T_ + t) * H_ + j] = hnew;
        }

        // Grid barrier: release (fence + leader atomic) / acquire (spin on gen).
        __threadfence();
        __syncthreads();
        if (tid == 0) {
            int target = t + 1;
            int old = atomicAdd(&g_bar_count, 1);
            if (old == NCTA - 1) {
                g_bar_count = 0;
                __threadfence();
                g_bar_gen = target;
            } else {
                while (g_bar_gen < target) __nanosleep(32);
            }
        }
        __syncthreads();
    }
}

// ---------------------------------------------------------------------------
// kernel_launch: zero, phase-1 GEMM, one persistent phase-2 kernel. 3 nodes.
// ---------------------------------------------------------------------------
extern "C" void kernel_launch(void* const* d_in, const int* in_sizes, int n_in,
                              void* d_out, int out_size) {
    const float* x   = (const float*)d_in[0];
    const float* wih = (const float*)d_in[1];
    const float* whh = (const float*)d_in[2];
    const float* bih = (const float*)d_in[3];
    const float* bhh = (const float*)d_in[4];
    float* out = (float*)d_out;

    const int smem2 = (B_ * H_ + 96 * WR) * (int)sizeof(float);  // 165,376 B
    cudaFuncSetAttribute(gru_persist_kernel,
                         cudaFuncAttributeMaxDynamicSharedMemorySize, smem2);

    zero_kernel<<<(2 * N_ * B_ * H_ + 255) / 256, 256>>>();
    ih_gemm_kernel<<<dim3(12, 128, 16), 256>>>(x, wih, bih);
    gru_persist_kernel<<<dim3(8, 16), 256, smem2>>>(whh, bhh, out);
}

// round 9
// speedup vs baseline: 1.3376x; 1.3376x over previous
#include <cuda_runtime.h>
#include <cuda_bf16.h>
#include <cstdint>

#define B_  64
#define N_  16
#define T_  128
#define I_  256
#define H_  256
#define G3  768    // 3*H
#define NCTA 128   // persistent-kernel CTA count
#define WR  260    // padded ws row length (floats), phase-2

// Scratch: input projection IH[n][t][b][g] (bih folded in), fp32.
__device__ float g_IH[(size_t)N_ * T_ * B_ * G3];
// hi/lo bf16 copies of x and wih.
__device__ __nv_bfloat16 g_xhi[(size_t)B_ * N_ * T_ * I_];
__device__ __nv_bfloat16 g_xlo[(size_t)B_ * N_ * T_ * I_];
__device__ __nv_bfloat16 g_whi[(size_t)N_ * G3 * I_];
__device__ __nv_bfloat16 g_wlo[(size_t)N_ * G3 * I_];
// Double-buffered hidden state h[2][n][b][k].
__device__ float g_h[2 * N_ * B_ * H_];
// Software grid barrier (reset per launch by zero_kernel).
__device__ int g_bar_count;
__device__ volatile int g_bar_gen;

// ---------------------------------------------------------------------------
__global__ void zero_kernel() {
    int i = blockIdx.x * blockDim.x + threadIdx.x;
    if (i < 2 * N_ * B_ * H_) g_h[i] = 0.0f;
    if (i == 0) { g_bar_count = 0; g_bar_gen = 0; }
}

// ---------------------------------------------------------------------------
// fp32 -> (hi, lo) bf16 split, writing directly to device globals.
// which=0: x (-> g_xhi/g_xlo), which=1: wih (-> g_whi/g_wlo).
// ---------------------------------------------------------------------------
__global__ void cvt_hilo_kernel(const float* __restrict__ src,
                                int which, size_t n4) {
    __nv_bfloat16* hi = which ? g_whi : g_xhi;
    __nv_bfloat16* lo = which ? g_wlo : g_xlo;
    for (size_t i = blockIdx.x * (size_t)blockDim.x + threadIdx.x; i < n4;
         i += (size_t)gridDim.x * blockDim.x) {
        float4 v = ((const float4*)src)[i];
        float vv[4] = {v.x, v.y, v.z, v.w};
        uint16_t hw[4], lw[4];
#pragma unroll
        for (int u = 0; u < 4; u++) {
            __nv_bfloat16 h = __float2bfloat16_rn(vv[u]);
            float r = vv[u] - __bfloat162float(h);
            __nv_bfloat16 l = __float2bfloat16_rn(r);
            hw[u] = __bfloat16_as_ushort(h);
            lw[u] = __bfloat16_as_ushort(l);
        }
        uint2 ho, lo2;
        ho.x  = (uint32_t)hw[0] | ((uint32_t)hw[1] << 16);
        ho.y  = (uint32_t)hw[2] | ((uint32_t)hw[3] << 16);
        lo2.x = (uint32_t)lw[0] | ((uint32_t)lw[1] << 16);
        lo2.y = (uint32_t)lw[2] | ((uint32_t)lw[3] << 16);
        ((uint2*)hi)[i] = ho;
        ((uint2*)lo)[i] = lo2;
    }
}

// ---------------------------------------------------------------------------
// mma.sync m16n8k16 bf16 (compute_100-legal legacy tensor path).
// ---------------------------------------------------------------------------
__device__ __forceinline__ void mma16816(float* c, const uint32_t* a,
                                         const uint32_t* b) {
    asm volatile(
        "mma.sync.aligned.m16n8k16.row.col.f32.bf16.bf16.f32 "
        "{%0,%1,%2,%3}, {%4,%5,%6,%7}, {%8,%9}, {%0,%1,%2,%3};"
        : "+f"(c[0]), "+f"(c[1]), "+f"(c[2]), "+f"(c[3])
        : "r"(a[0]), "r"(a[1]), "r"(a[2]), "r"(a[3]), "r"(b[0]), "r"(b[1]));
}

// Smem tile geometry: [128 rows][64 k] bf16, rows padded to 72 (conflict-free).
#define KT   64
#define SROW 72
#define TILE_ELE (128 * SROW)

// ---------------------------------------------------------------------------
// Phase 1: IH = x . Wih^T + bih on tensor cores, hi/lo bf16 3-pass.
// Grid (mt=64 [=b], gt=6, n=16), 256 threads (8 warps: wm=wid&1, wn=wid>>1).
// Each warp: 64x32 output = 4x4 m16n8 frags, K=256 in 4 tiles of 64.
// ---------------------------------------------------------------------------
__global__ void __launch_bounds__(256, 2)
ih_mma_kernel(const float* __restrict__ bih) {
    extern __shared__ __nv_bfloat16 smem[];
    __nv_bfloat16* SAH = smem;
    __nv_bfloat16* SAL = smem + TILE_ELE;
    __nv_bfloat16* SBH = smem + 2 * TILE_ELE;
    __nv_bfloat16* SBL = smem + 3 * TILE_ELE;

    const int mt  = blockIdx.x;          // = b
    const int gt  = blockIdx.y;          // gate tile (128 gates)
    const int n   = blockIdx.z;
    const int tid = threadIdx.x;
    const int wid = tid >> 5;
    const int lane = tid & 31;
    const int wm  = wid & 1;             // 0..1 (64-row half)
    const int wn  = wid >> 1;            // 0..3 (32-col quarter)
    const int g   = lane >> 2;           // 0..7
    const int tig = lane & 3;            // 0..3

    const __nv_bfloat16* axh = g_xhi + ((size_t)(mt * N_ + n)) * T_ * I_;
    const __nv_bfloat16* axl = g_xlo + ((size_t)(mt * N_ + n)) * T_ * I_;
    const __nv_bfloat16* bwh = g_whi + ((size_t)(n * G3 + gt * 128)) * I_;
    const __nv_bfloat16* bwl = g_wlo + ((size_t)(n * G3 + gt * 128)) * I_;

    float acc[4][4][4];
#pragma unroll
    for (int mi = 0; mi < 4; mi++)
#pragma unroll
        for (int ni = 0; ni < 4; ni++)
#pragma unroll
            for (int u = 0; u < 4; u++) acc[mi][ni][u] = 0.0f;

    for (int kt = 0; kt < I_; kt += KT) {
        // Stage 4 tiles: [128 rows][64 bf16] each = 1024 uint4 segments
        // (8 segments of 8 bf16 per row). 4 segments per thread per matrix.
#pragma unroll
        for (int l = 0; l < 4; l++) {
            int it = tid + (l << 8);     // 0..1023
            int r = it >> 3;             // row 0..127
            int q = it & 7;              // 16B segment 0..7
            size_t goff = (size_t)r * I_ + kt + q * 8;
            int soff = r * SROW + q * 8;
            *(uint4*)(SAH + soff) = *(const uint4*)(axh + goff);
            *(uint4*)(SAL + soff) = *(const uint4*)(axl + goff);
            *(uint4*)(SBH + soff) = *(const uint4*)(bwh + goff);
            *(uint4*)(SBL + soff) = *(const uint4*)(bwl + goff);
        }
        __syncthreads();

#pragma unroll
        for (int kk = 0; kk < KT; kk += 16) {
            uint32_t af[4][4], bh[4][2], bl[4][2];
            const int k0 = kk + 2 * tig;
#pragma unroll
            for (int mi = 0; mi < 4; mi++) {
                int rb = wm * 64 + mi * 16;
                af[mi][0] = *(const uint32_t*)(SAH + (rb + g) * SROW + k0);
                af[mi][1] = *(const uint32_t*)(SAH + (rb + g + 8) * SROW + k0);
                af[mi][2] = *(const uint32_t*)(SAH + (rb + g) * SROW + k0 + 8);
                af[mi][3] = *(const uint32_t*)(SAH + (rb + g + 8) * SROW + k0 + 8);
            }
#pragma unroll
            for (int ni = 0; ni < 4; ni++) {
                int nb = wn * 32 + ni * 8;
                bh[ni][0] = *(const uint32_t*)(SBH + (nb + g) * SROW + k0);
                bh[ni][1] = *(const uint32_t*)(SBH + (nb + g) * SROW + k0 + 8);
                bl[ni][0] = *(const uint32_t*)(SBL + (nb + g) * SROW + k0);
                bl[ni][1] = *(const uint32_t*)(SBL + (nb + g) * SROW + k0 + 8);
            }
            // Pass 1: Ahi x Bhi ; Pass 2: Ahi x Blo
#pragma unroll
            for (int mi = 0; mi < 4; mi++)
#pragma unroll
                for (int ni = 0; ni < 4; ni++) {
                    mma16816(acc[mi][ni], af[mi], bh[ni]);
                    mma16816(acc[mi][ni], af[mi], bl[ni]);
                }
            // Pass 3: Alo x Bhi (reuse af registers)
#pragma unroll
            for (int mi = 0; mi < 4; mi++) {
                int rb = wm * 64 + mi * 16;
                af[mi][0] = *(const uint32_t*)(SAL + (rb + g) * SROW + k0);
                af[mi][1] = *(const uint32_t*)(SAL + (rb + g + 8) * SROW + k0);
                af[mi][2] = *(const uint32_t*)(SAL + (rb + g) * SROW + k0 + 8);
                af[mi][3] = *(const uint32_t*)(SAL + (rb + g + 8) * SROW + k0 + 8);
            }
#pragma unroll
            for (int mi = 0; mi < 4; mi++)
#pragma unroll
                for (int ni = 0; ni < 4; ni++)
                    mma16816(acc[mi][ni], af[mi], bh[ni]);
        }
        __syncthreads();
    }

    // Epilogue: bias add + fp32 store to g_IH[n][t][b][g3].  (t = row, b = mt)
#pragma unroll
    for (int ni = 0; ni < 4; ni++) {
        const int col = gt * 128 + wn * 32 + ni * 8 + 2 * tig;
        const float2 bias = *(const float2*)(bih + n * G3 + col);
#pragma unroll
        for (int mi = 0; mi < 4; mi++) {
            int row = wm * 64 + mi * 16 + g;       // = t
            float2 o0, o1;
            o0.x = acc[mi][ni][0] + bias.x;
            o0.y = acc[mi][ni][1] + bias.y;
            o1.x = acc[mi][ni][2] + bias.x;
            o1.y = acc[mi][ni][3] + bias.y;
            *(float2*)(g_IH + (((size_t)(n * T_ + row)) * B_ + mt) * G3 + col) = o0;
            *(float2*)(g_IH + (((size_t)(n * T_ + row + 8)) * B_ + mt) * G3 + col) = o1;
        }
    }
}

// ---------------------------------------------------------------------------
// Phase 2: ONE persistent kernel, 128 timesteps, software grid barrier.
// (unchanged from the passing R3/R4 kernel)
// ---------------------------------------------------------------------------
__global__ void __launch_bounds__(256, 1)
gru_persist_kernel(const float* __restrict__ whh,
                   const float* __restrict__ bhh,
                   float* __restrict__ out) {
    extern __shared__ float sm[];
    float* hs = sm;                 // [64][256] staged h_prev
    float* ws = sm + B_ * H_;       // [96][WR] weights

    const int n    = blockIdx.y;
    const int jc   = blockIdx.x;
    const int tid  = threadIdx.x;
    const int lane = tid & 31;
    const int wrp  = tid >> 5;
    const int j    = (jc << 5) + lane;

    for (int it = tid; it < 96 * 64; it += 256) {
        int row  = it >> 6;
        int q    = it & 63;
        int gate = row >> 5;
        int jl   = row & 31;
        float4 wv = *(const float4*)(whh +
            ((size_t)(n * G3 + gate * H_ + (jc << 5) + jl)) * H_ + (q << 2));
        float* d = ws + (size_t)row * WR + (q << 2);
        d[0] = wv.x; d[1] = wv.y; d[2] = wv.z; d[3] = wv.w;
    }
    const float bhr = bhh[n * G3 + j];
    const float bhz = bhh[n * G3 + H_ + j];
    const float bhn = bhh[n * G3 + 2 * H_ + j];
    __syncthreads();

    const float* wrow_r = ws + (0 * 32 + lane) * WR;
    const float* wrow_z = ws + (1 * 32 + lane) * WR;
    const float* wrow_n = ws + (2 * 32 + lane) * WR;

    for (int t = 0; t < T_; t++) {
        const float* hsrc = g_h + (t & 1) * (N_ * B_ * H_) + n * (B_ * H_);
        for (int i = tid; i < (B_ * H_) / 4; i += 256)
            ((float4*)hs)[i] = __ldcg(((const float4*)hsrc) + i);
        __syncthreads();

        float accr[8], accz[8], accn[8];
#pragma unroll
        for (int i = 0; i < 8; i++) { accr[i] = 0.f; accz[i] = 0.f; accn[i] = 0.f; }

        const float* hbase = hs + (wrp << 3) * H_;
#pragma unroll 4
        for (int kq = 0; kq < H_; kq += 4) {
            float4 wr4 = *(const float4*)(wrow_r + kq);
            float4 wz4 = *(const float4*)(wrow_z + kq);
            float4 wn4 = *(const float4*)(wrow_n + kq);
#pragma unroll
            for (int i = 0; i < 8; i++) {
                float4 hv = *(const float4*)(hbase + i * H_ + kq);
                accr[i] = fmaf(hv.x, wr4.x, accr[i]);
                accr[i] = fmaf(hv.y, wr4.y, accr[i]);
                accr[i] = fmaf(hv.z, wr4.z, accr[i]);
                accr[i] = fmaf(hv.w, wr4.w, accr[i]);
                accz[i] = fmaf(hv.x, wz4.x, accz[i]);
                accz[i] = fmaf(hv.y, wz4.y, accz[i]);
                accz[i] = fmaf(hv.z, wz4.z, accz[i]);
                accz[i] = fmaf(hv.w, wz4.w, accz[i]);
                accn[i] = fmaf(hv.x, wn4.x, accn[i]);
                accn[i] = fmaf(hv.y, wn4.y, accn[i]);
                accn[i] = fmaf(hv.z, wn4.z, accn[i]);
                accn[i] = fmaf(hv.w, wn4.w, accn[i]);
            }
        }

        const float* ihb = g_IH + ((size_t)(n * T_ + t) * B_) * G3;
        float* hdst = g_h + ((t + 1) & 1) * (N_ * B_ * H_) + n * (B_ * H_);
#pragma unroll
        for (int i = 0; i < 8; i++) {
            int b = (wrp << 3) + i;
            float ihr = ihb[(size_t)b * G3 + j];
            float ihz = ihb[(size_t)b * G3 + H_ + j];
            float ihn = ihb[(size_t)b * G3 + 2 * H_ + j];
            float hr = accr[i] + bhr;
            float hz = accz[i] + bhz;
            float hn = accn[i] + bhn;
            float rg = 1.0f / (1.0f + __expf(-(ihr + hr)));
            float zg = 1.0f / (1.0f + __expf(-(ihz + hz)));
            float ng = tanhf(ihn + rg * hn);
            float hp = hs[b * H_ + j];
            float hnew = (1.0f - zg) * ng + zg * hp;
            hdst[b * H_ + j] = hnew;
            out[((size_t)(b * N_ + n) * T_ + t) * H_ + j] = hnew;
        }

        __threadfence();
        __syncthreads();
        if (tid == 0) {
            int target = t + 1;
            int old = atomicAdd(&g_bar_count, 1);
            if (old == NCTA - 1) {
                g_bar_count = 0;
                __threadfence();
                g_bar_gen = target;
            } else {
                while (g_bar_gen < target) __nanosleep(32);
            }
        }
        __syncthreads();
    }
}

// ---------------------------------------------------------------------------
// kernel_launch: zero, cvt x, cvt w, mma phase-1, persistent phase-2.
// ---------------------------------------------------------------------------
extern "C" void kernel_launch(void* const* d_in, const int* in_sizes, int n_in,
                              void* d_out, int out_size) {
    const float* x   = (const float*)d_in[0];
    const float* wih = (const float*)d_in[1];
    const float* whh = (const float*)d_in[2];
    const float* bih = (const float*)d_in[3];
    const float* bhh = (const float*)d_in[4];
    float* out = (float*)d_out;

    const int smem1 = 4 * TILE_ELE * (int)sizeof(__nv_bfloat16);   // 73,728 B
    const int smem2 = (B_ * H_ + 96 * WR) * (int)sizeof(float);    // 165,376 B
    cudaFuncSetAttribute(ih_mma_kernel,
                         cudaFuncAttributeMaxDynamicSharedMemorySize, smem1);
    cudaFuncSetAttribute(gru_persist_kernel,
                         cudaFuncAttributeMaxDynamicSharedMemorySize, smem2);

    zero_kernel<<<(2 * N_ * B_ * H_ + 255) / 256, 256>>>();

    const size_t nx4 = (size_t)B_ * N_ * T_ * I_ / 4;
    const size_t nw4 = (size_t)N_ * G3 * I_ / 4;
    cvt_hilo_kernel<<<4096, 256>>>(x, 0, nx4);
    cvt_hilo_kernel<<<1024, 256>>>(wih, 1, nw4);

    ih_mma_kernel<<<dim3(64, 6, 16), 256, smem1>>>(bih);
    gru_persist_kernel<<<dim3(8, 16), 256, smem2>>>(whh, bhh, out);
}

// round 10
// speedup vs baseline: 2.1178x; 1.5832x over previous
#include <cuda_runtime.h>
#include <cuda_bf16.h>
#include <cstdint>

#define B_  64
#define N_  16
#define T_  128
#define I_  256
#define H_  256
#define G3  768    // 3*H
#define NCTA 128   // persistent-kernel CTA count

// Scratch: input projection IH[n][t][b][g] (bih folded in), fp32.
__device__ float g_IH[(size_t)N_ * T_ * B_ * G3];
// hi/lo bf16 copies of x and wih (phase 1).
__device__ __nv_bfloat16 g_xhi[(size_t)B_ * N_ * T_ * I_];
__device__ __nv_bfloat16 g_xlo[(size_t)B_ * N_ * T_ * I_];
__device__ __nv_bfloat16 g_whi[(size_t)N_ * G3 * I_];
__device__ __nv_bfloat16 g_wlo[(size_t)N_ * G3 * I_];
// Double-buffered hidden state as hi/lo bf16 pairs: [2][n][b][k].
__device__ __nv_bfloat16 g_hhi[2 * N_ * B_ * H_];
__device__ __nv_bfloat16 g_hlo[2 * N_ * B_ * H_];
// Software grid barrier (reset per launch by zero_kernel).
__device__ int g_bar_count;
__device__ volatile int g_bar_gen;

// ---------------------------------------------------------------------------
__global__ void zero_kernel() {
    int i = blockIdx.x * blockDim.x + threadIdx.x;
    // 2*16*64*256 bf16 = 1 MB per array = 65536 uint4 each.
    if (i < 65536) {
        ((uint4*)g_hhi)[i] = make_uint4(0, 0, 0, 0);
        ((uint4*)g_hlo)[i] = make_uint4(0, 0, 0, 0);
    }
    if (i == 0) { g_bar_count = 0; g_bar_gen = 0; }
}

// ---------------------------------------------------------------------------
// fp32 -> (hi, lo) bf16 split, writing directly to device globals.
// which=0: x (-> g_xhi/g_xlo), which=1: wih (-> g_whi/g_wlo).
// ---------------------------------------------------------------------------
__global__ void cvt_hilo_kernel(const float* __restrict__ src,
                                int which, size_t n4) {
    __nv_bfloat16* hi = which ? g_whi : g_xhi;
    __nv_bfloat16* lo = which ? g_wlo : g_xlo;
    for (size_t i = blockIdx.x * (size_t)blockDim.x + threadIdx.x; i < n4;
         i += (size_t)gridDim.x * blockDim.x) {
        float4 v = ((const float4*)src)[i];
        float vv[4] = {v.x, v.y, v.z, v.w};
        uint16_t hw[4], lw[4];
#pragma unroll
        for (int u = 0; u < 4; u++) {
            __nv_bfloat16 h = __float2bfloat16_rn(vv[u]);
            float r = vv[u] - __bfloat162float(h);
            __nv_bfloat16 l = __float2bfloat16_rn(r);
            hw[u] = __bfloat16_as_ushort(h);
            lw[u] = __bfloat16_as_ushort(l);
        }
        uint2 ho, lo2;
        ho.x  = (uint32_t)hw[0] | ((uint32_t)hw[1] << 16);
        ho.y  = (uint32_t)hw[2] | ((uint32_t)hw[3] << 16);
        lo2.x = (uint32_t)lw[0] | ((uint32_t)lw[1] << 16);
        lo2.y = (uint32_t)lw[2] | ((uint32_t)lw[3] << 16);
        ((uint2*)hi)[i] = ho;
        ((uint2*)lo)[i] = lo2;
    }
}

// ---------------------------------------------------------------------------
// mma.sync m16n8k16 bf16.
// ---------------------------------------------------------------------------
__device__ __forceinline__ void mma16816(float* c, const uint32_t* a,
                                         const uint32_t* b) {
    asm volatile(
        "mma.sync.aligned.m16n8k16.row.col.f32.bf16.bf16.f32 "
        "{%0,%1,%2,%3}, {%4,%5,%6,%7}, {%8,%9}, {%0,%1,%2,%3};"
        : "+f"(c[0]), "+f"(c[1]), "+f"(c[2]), "+f"(c[3])
        : "r"(a[0]), "r"(a[1]), "r"(a[2]), "r"(a[3]), "r"(b[0]), "r"(b[1]));
}

// ============================ PHASE 1 (unchanged, validated) ================
#define KT   64
#define SROW 72
#define TILE_ELE (128 * SROW)

__global__ void __launch_bounds__(256, 2)
ih_mma_kernel(const float* __restrict__ bih) {
    extern __shared__ __nv_bfloat16 smem[];
    __nv_bfloat16* SAH = smem;
    __nv_bfloat16* SAL = smem + TILE_ELE;
    __nv_bfloat16* SBH = smem + 2 * TILE_ELE;
    __nv_bfloat16* SBL = smem + 3 * TILE_ELE;

    const int mt  = blockIdx.x;
    const int gt  = blockIdx.y;
    const int n   = blockIdx.z;
    const int tid = threadIdx.x;
    const int wid = tid >> 5;
    const int lane = tid & 31;
    const int wm  = wid & 1;
    const int wn  = wid >> 1;
    const int g   = lane >> 2;
    const int tig = lane & 3;

    const __nv_bfloat16* axh = g_xhi + ((size_t)(mt * N_ + n)) * T_ * I_;
    const __nv_bfloat16* axl = g_xlo + ((size_t)(mt * N_ + n)) * T_ * I_;
    const __nv_bfloat16* bwh = g_whi + ((size_t)(n * G3 + gt * 128)) * I_;
    const __nv_bfloat16* bwl = g_wlo + ((size_t)(n * G3 + gt * 128)) * I_;

    float acc[4][4][4];
#pragma unroll
    for (int mi = 0; mi < 4; mi++)
#pragma unroll
        for (int ni = 0; ni < 4; ni++)
#pragma unroll
            for (int u = 0; u < 4; u++) acc[mi][ni][u] = 0.0f;

    for (int kt = 0; kt < I_; kt += KT) {
#pragma unroll
        for (int l = 0; l < 4; l++) {
            int it = tid + (l << 8);
            int r = it >> 3;
            int q = it & 7;
            size_t goff = (size_t)r * I_ + kt + q * 8;
            int soff = r * SROW + q * 8;
            *(uint4*)(SAH + soff) = *(const uint4*)(axh + goff);
            *(uint4*)(SAL + soff) = *(const uint4*)(axl + goff);
            *(uint4*)(SBH + soff) = *(const uint4*)(bwh + goff);
            *(uint4*)(SBL + soff) = *(const uint4*)(bwl + goff);
        }
        __syncthreads();

#pragma unroll
        for (int kk = 0; kk < KT; kk += 16) {
            uint32_t af[4][4], bh[4][2], bl[4][2];
            const int k0 = kk + 2 * tig;
#pragma unroll
            for (int mi = 0; mi < 4; mi++) {
                int rb = wm * 64 + mi * 16;
                af[mi][0] = *(const uint32_t*)(SAH + (rb + g) * SROW + k0);
                af[mi][1] = *(const uint32_t*)(SAH + (rb + g + 8) * SROW + k0);
                af[mi][2] = *(const uint32_t*)(SAH + (rb + g) * SROW + k0 + 8);
                af[mi][3] = *(const uint32_t*)(SAH + (rb + g + 8) * SROW + k0 + 8);
            }
#pragma unroll
            for (int ni = 0; ni < 4; ni++) {
                int nb = wn * 32 + ni * 8;
                bh[ni][0] = *(const uint32_t*)(SBH + (nb + g) * SROW + k0);
                bh[ni][1] = *(const uint32_t*)(SBH + (nb + g) * SROW + k0 + 8);
                bl[ni][0] = *(const uint32_t*)(SBL + (nb + g) * SROW + k0);
                bl[ni][1] = *(const uint32_t*)(SBL + (nb + g) * SROW + k0 + 8);
            }
#pragma unroll
            for (int mi = 0; mi < 4; mi++)
#pragma unroll
                for (int ni = 0; ni < 4; ni++) {
                    mma16816(acc[mi][ni], af[mi], bh[ni]);
                    mma16816(acc[mi][ni], af[mi], bl[ni]);
                }
#pragma unroll
            for (int mi = 0; mi < 4; mi++) {
                int rb = wm * 64 + mi * 16;
                af[mi][0] = *(const uint32_t*)(SAL + (rb + g) * SROW + k0);
                af[mi][1] = *(const uint32_t*)(SAL + (rb + g + 8) * SROW + k0);
                af[mi][2] = *(const uint32_t*)(SAL + (rb + g) * SROW + k0 + 8);
                af[mi][3] = *(const uint32_t*)(SAL + (rb + g + 8) * SROW + k0 + 8);
            }
#pragma unroll
            for (int mi = 0; mi < 4; mi++)
#pragma unroll
                for (int ni = 0; ni < 4; ni++)
                    mma16816(acc[mi][ni], af[mi], bh[ni]);
        }
        __syncthreads();
    }

#pragma unroll
    for (int ni = 0; ni < 4; ni++) {
        const int col = gt * 128 + wn * 32 + ni * 8 + 2 * tig;
        const float2 bias = *(const float2*)(bih + n * G3 + col);
#pragma unroll
        for (int mi = 0; mi < 4; mi++) {
            int row = wm * 64 + mi * 16 + g;
            float2 o0, o1;
            o0.x = acc[mi][ni][0] + bias.x;
            o0.y = acc[mi][ni][1] + bias.y;
            o1.x = acc[mi][ni][2] + bias.x;
            o1.y = acc[mi][ni][3] + bias.y;
            *(float2*)(g_IH + (((size_t)(n * T_ + row)) * B_ + mt) * G3 + col) = o0;
            *(float2*)(g_IH + (((size_t)(n * T_ + row + 8)) * B_ + mt) * G3 + col) = o1;
        }
    }
}

// ============================ PHASE 2: tensor-core persistent ==============
// Grid (jc=8, n=16) = 128 CTAs, 256 threads (8 warps: wm=wid&1, wn=wid>>1).
// Whh slice [96 rows = gate*32+jl][256 k] hi/lo bf16 resident in smem.
// h state: gmem double-buffered hi/lo bf16; staged to smem each step.
// Warp output: 32 b-rows (2 m16 frags) x [3 gates x 8 j] (3 n8 frags).
// ---------------------------------------------------------------------------
#define WPAD 264   // padded row length (bf16): frag banks (4g+tig) conflict-free

__global__ void __launch_bounds__(256, 1)
gru_mma_kernel(const float* __restrict__ whh,
               const float* __restrict__ bhh,
               float* __restrict__ out) {
    extern __shared__ __nv_bfloat16 sm2[];
    __nv_bfloat16* wsh = sm2;                 // [96][WPAD]
    __nv_bfloat16* wsl = wsh + 96 * WPAD;
    __nv_bfloat16* hsh = wsl + 96 * WPAD;     // [64][WPAD]
    __nv_bfloat16* hsl = hsh + 64 * WPAD;

    const int n    = blockIdx.y;
    const int jc   = blockIdx.x;
    const int tid  = threadIdx.x;
    const int wid  = tid >> 5;
    const int lane = tid & 31;
    const int wm   = wid & 1;     // 32-row b half
    const int wn   = wid >> 1;    // 8-j quarter
    const int g    = lane >> 2;   // 0..7
    const int tig  = lane & 3;    // 0..3

    // Convert Whh slice fp32 -> hi/lo bf16 smem (once). 96 rows x 64 float4.
    for (int it = tid; it < 96 * 64; it += 256) {
        int row  = it >> 6;                // gate*32 + jl
        int q    = it & 63;                // float4 index (k = 4q)
        int gate = row >> 5;
        int jl   = row & 31;
        const float4 wv = *(const float4*)(whh +
            ((size_t)(n * G3 + gate * H_ + jc * 32 + jl)) * H_ + q * 4);
        float v[4] = {wv.x, wv.y, wv.z, wv.w};
        uint32_t hw[2], lw[2];
#pragma unroll
        for (int u = 0; u < 2; u++) {
            __nv_bfloat16 h0 = __float2bfloat16_rn(v[2 * u]);
            __nv_bfloat16 h1 = __float2bfloat16_rn(v[2 * u + 1]);
            float r0 = v[2 * u]     - __bfloat162float(h0);
            float r1 = v[2 * u + 1] - __bfloat162float(h1);
            hw[u] = (uint32_t)__bfloat16_as_ushort(h0) |
                    ((uint32_t)__bfloat16_as_ushort(h1) << 16);
            lw[u] = (uint32_t)__bfloat16_as_ushort(__float2bfloat16_rn(r0)) |
                    ((uint32_t)__bfloat16_as_ushort(__float2bfloat16_rn(r1)) << 16);
        }
        *(uint2*)(wsh + row * WPAD + q * 4) = make_uint2(hw[0], hw[1]);
        *(uint2*)(wsl + row * WPAD + q * 4) = make_uint2(lw[0], lw[1]);
    }

    // Per-thread fixed output columns (j pair) and biases.
    const int jg0 = jc * 32 + wn * 8 + 2 * tig;    // hidden index 0..255
    const float2 bhr2 = *(const float2*)(bhh + n * G3 + jg0);
    const float2 bhz2 = *(const float2*)(bhh + n * G3 + H_ + jg0);
    const float2 bhn2 = *(const float2*)(bhh + n * G3 + 2 * H_ + jg0);

    for (int t = 0; t < T_; t++) {
        // Stage h (hi/lo bf16): 64 rows x 32 uint4 per matrix.
        const __nv_bfloat16* hhsrc = g_hhi + ((size_t)((t & 1) * N_ + n)) * B_ * H_;
        const __nv_bfloat16* hlsrc = g_hlo + ((size_t)((t & 1) * N_ + n)) * B_ * H_;
        __syncthreads();   // t=0: covers W staging; t>0: guard smem reuse vs epilogue reads
        for (int it = tid; it < 2048; it += 256) {
            int r = it >> 5, q = it & 31;
            *(uint4*)(hsh + r * WPAD + q * 8) =
                __ldcg((const uint4*)(hhsrc + r * H_ + q * 8));
            *(uint4*)(hsl + r * WPAD + q * 8) =
                __ldcg((const uint4*)(hlsrc + r * H_ + q * 8));
        }
        __syncthreads();

        float acc[2][3][4];
#pragma unroll
        for (int mi = 0; mi < 2; mi++)
#pragma unroll
            for (int ni = 0; ni < 3; ni++)
#pragma unroll
                for (int u = 0; u < 4; u++) acc[mi][ni][u] = 0.0f;

#pragma unroll
        for (int kk = 0; kk < H_; kk += 16) {
            const int k0 = kk + 2 * tig;
            uint32_t ah[2][4], al[2][4], bh[3][2], bl[3][2];
#pragma unroll
            for (int mi = 0; mi < 2; mi++) {
                int rb = wm * 32 + mi * 16;
                ah[mi][0] = *(const uint32_t*)(hsh + (rb + g) * WPAD + k0);
                ah[mi][1] = *(const uint32_t*)(hsh + (rb + g + 8) * WPAD + k0);
                ah[mi][2] = *(const uint32_t*)(hsh + (rb + g) * WPAD + k0 + 8);
                ah[mi][3] = *(const uint32_t*)(hsh + (rb + g + 8) * WPAD + k0 + 8);
                al[mi][0] = *(const uint32_t*)(hsl + (rb + g) * WPAD + k0);
                al[mi][1] = *(const uint32_t*)(hsl + (rb + g + 8) * WPAD + k0);
                al[mi][2] = *(const uint32_t*)(hsl + (rb + g) * WPAD + k0 + 8);
                al[mi][3] = *(const uint32_t*)(hsl + (rb + g + 8) * WPAD + k0 + 8);
            }
#pragma unroll
            for (int ni = 0; ni < 3; ni++) {
                int nb = ni * 32 + wn * 8;     // gate-major columns
                bh[ni][0] = *(const uint32_t*)(wsh + (nb + g) * WPAD + k0);
                bh[ni][1] = *(const uint32_t*)(wsh + (nb + g) * WPAD + k0 + 8);
                bl[ni][0] = *(const uint32_t*)(wsl + (nb + g) * WPAD + k0);
                bl[ni][1] = *(const uint32_t*)(wsl + (nb + g) * WPAD + k0 + 8);
            }
#pragma unroll
            for (int mi = 0; mi < 2; mi++)
#pragma unroll
                for (int ni = 0; ni < 3; ni++) {
                    mma16816(acc[mi][ni], ah[mi], bh[ni]);
                    mma16816(acc[mi][ni], ah[mi], bl[ni]);
                    mma16816(acc[mi][ni], al[mi], bh[ni]);
                }
        }

        // Fused gate epilogue. Each thread: 2 mi x 2 rowpair x 2 cols outputs.
        const float* ihb = g_IH + ((size_t)(n * T_ + t) * B_) * G3;
        const int buf = (t + 1) & 1;
        __nv_bfloat16* hhdst = g_hhi + ((size_t)(buf * N_ + n)) * B_ * H_;
        __nv_bfloat16* hldst = g_hlo + ((size_t)(buf * N_ + n)) * B_ * H_;

#pragma unroll
        for (int mi = 0; mi < 2; mi++)
#pragma unroll
            for (int rr = 0; rr < 2; rr++) {
                const int b  = wm * 32 + mi * 16 + g + rr * 8;
                const int ci = rr * 2;
                float2 ihr = *(const float2*)(ihb + (size_t)b * G3 + jg0);
                float2 ihz = *(const float2*)(ihb + (size_t)b * G3 + H_ + jg0);
                float2 ihn = *(const float2*)(ihb + (size_t)b * G3 + 2 * H_ + jg0);
                float hp0 = __bfloat162float(hsh[b * WPAD + jg0]) +
                            __bfloat162float(hsl[b * WPAD + jg0]);
                float hp1 = __bfloat162float(hsh[b * WPAD + jg0 + 1]) +
                            __bfloat162float(hsl[b * WPAD + jg0 + 1]);
                float hr0 = acc[mi][0][ci]     + bhr2.x;
                float hr1 = acc[mi][0][ci + 1] + bhr2.y;
                float hz0 = acc[mi][1][ci]     + bhz2.x;
                float hz1 = acc[mi][1][ci + 1] + bhz2.y;
                float hn0 = acc[mi][2][ci]     + bhn2.x;
                float hn1 = acc[mi][2][ci + 1] + bhn2.y;
                float rg0 = 1.0f / (1.0f + __expf(-(ihr.x + hr0)));
                float rg1 = 1.0f / (1.0f + __expf(-(ihr.y + hr1)));
                float zg0 = 1.0f / (1.0f + __expf(-(ihz.x + hz0)));
                float zg1 = 1.0f / (1.0f + __expf(-(ihz.y + hz1)));
                float ng0 = tanhf(ihn.x + rg0 * hn0);
                float ng1 = tanhf(ihn.y + rg1 * hn1);
                float h0 = (1.0f - zg0) * ng0 + zg0 * hp0;
                float h1 = (1.0f - zg1) * ng1 + zg1 * hp1;

                float2 o; o.x = h0; o.y = h1;
                *(float2*)(out + ((size_t)(b * N_ + n) * T_ + t) * H_ + jg0) = o;

                __nv_bfloat16 hi0 = __float2bfloat16_rn(h0);
                __nv_bfloat16 hi1 = __float2bfloat16_rn(h1);
                __nv_bfloat16 lo0 = __float2bfloat16_rn(h0 - __bfloat162float(hi0));
                __nv_bfloat16 lo1 = __float2bfloat16_rn(h1 - __bfloat162float(hi1));
                *(uint32_t*)(hhdst + (size_t)b * H_ + jg0) =
                    (uint32_t)__bfloat16_as_ushort(hi0) |
                    ((uint32_t)__bfloat16_as_ushort(hi1) << 16);
                *(uint32_t*)(hldst + (size_t)b * H_ + jg0) =
                    (uint32_t)__bfloat16_as_ushort(lo0) |
                    ((uint32_t)__bfloat16_as_ushort(lo1) << 16);
            }

        // Grid barrier.
        __threadfence();
        __syncthreads();
        if (tid == 0) {
            int target = t + 1;
            int old = atomicAdd(&g_bar_count, 1);
            if (old == NCTA - 1) {
                g_bar_count = 0;
                __threadfence();
                g_bar_gen = target;
            } else {
                while (g_bar_gen < target) __nanosleep(32);
            }
        }
        __syncthreads();
    }
}

// ---------------------------------------------------------------------------
// kernel_launch
// ---------------------------------------------------------------------------
extern "C" void kernel_launch(void* const* d_in, const int* in_sizes, int n_in,
                              void* d_out, int out_size) {
    const float* x   = (const float*)d_in[0];
    const float* wih = (const float*)d_in[1];
    const float* whh = (const float*)d_in[2];
    const float* bih = (const float*)d_in[3];
    const float* bhh = (const float*)d_in[4];
    float* out = (float*)d_out;

    const int smem1 = 4 * TILE_ELE * (int)sizeof(__nv_bfloat16);       // 73,728 B
    const int smem2 = (2 * 96 * WPAD + 2 * 64 * WPAD) *
                      (int)sizeof(__nv_bfloat16);                      // 168,960 B
    cudaFuncSetAttribute(ih_mma_kernel,
                         cudaFuncAttributeMaxDynamicSharedMemorySize, smem1);
    cudaFuncSetAttribute(gru_mma_kernel,
                         cudaFuncAttributeMaxDynamicSharedMemorySize, smem2);

    zero_kernel<<<256, 256>>>();

    const size_t nx4 = (size_t)B_ * N_ * T_ * I_ / 4;
    const size_t nw4 = (size_t)N_ * G3 * I_ / 4;
    cvt_hilo_kernel<<<4096, 256>>>(x, 0, nx4);
    cvt_hilo_kernel<<<1024, 256>>>(wih, 1, nw4);

    ih_mma_kernel<<<dim3(64, 6, 16), 256, smem1>>>(bih);
    gru_mma_kernel<<<dim3(8, 16), 256, smem2>>>(whh, bhh, out);
}

// round 12
// speedup vs baseline: 2.1360x; 1.0086x over previous
#include <cuda_runtime.h>
#include <cuda_bf16.h>
#include <cstdint>

#define B_  64
#define N_  16
#define T_  128
#define I_  256
#define H_  256
#define G3  768    // 3*H
#define NCTA 128   // persistent-kernel CTA count

// Scratch: input projection IH[n][t][b][g] (bih folded in), fp32.
__device__ float g_IH[(size_t)N_ * T_ * B_ * G3];
// hi/lo bf16 copies of x and wih (phase 1).
__device__ __nv_bfloat16 g_xhi[(size_t)B_ * N_ * T_ * I_];
__device__ __nv_bfloat16 g_xlo[(size_t)B_ * N_ * T_ * I_];
__device__ __nv_bfloat16 g_whi[(size_t)N_ * G3 * I_];
__device__ __nv_bfloat16 g_wlo[(size_t)N_ * G3 * I_];
// Double-buffered hidden state as hi/lo bf16 pairs: [2][n][b][k].
__device__ __nv_bfloat16 g_hhi[2 * N_ * B_ * H_];
__device__ __nv_bfloat16 g_hlo[2 * N_ * B_ * H_];
// Software grid barrier (reset per launch by zero_kernel).
__device__ int g_bar_count;
__device__ volatile int g_bar_gen;

// ---------------------------------------------------------------------------
__global__ void zero_kernel() {
    int i = blockIdx.x * blockDim.x + threadIdx.x;
    if (i < 65536) {
        ((uint4*)g_hhi)[i] = make_uint4(0, 0, 0, 0);
        ((uint4*)g_hlo)[i] = make_uint4(0, 0, 0, 0);
    }
    if (i == 0) { g_bar_count = 0; g_bar_gen = 0; }
}

// ---------------------------------------------------------------------------
// fp32 -> (hi, lo) bf16 split, writing directly to device globals.
// ---------------------------------------------------------------------------
__global__ void cvt_hilo_kernel(const float* __restrict__ src,
                                int which, size_t n4) {
    __nv_bfloat16* hi = which ? g_whi : g_xhi;
    __nv_bfloat16* lo = which ? g_wlo : g_xlo;
    for (size_t i = blockIdx.x * (size_t)blockDim.x + threadIdx.x; i < n4;
         i += (size_t)gridDim.x * blockDim.x) {
        float4 v = ((const float4*)src)[i];
        float vv[4] = {v.x, v.y, v.z, v.w};
        uint16_t hw[4], lw[4];
#pragma unroll
        for (int u = 0; u < 4; u++) {
            __nv_bfloat16 h = __float2bfloat16_rn(vv[u]);
            float r = vv[u] - __bfloat162float(h);
            __nv_bfloat16 l = __float2bfloat16_rn(r);
            hw[u] = __bfloat16_as_ushort(h);
            lw[u] = __bfloat16_as_ushort(l);
        }
        uint2 ho, lo2;
        ho.x  = (uint32_t)hw[0] | ((uint32_t)hw[1] << 16);
        ho.y  = (uint32_t)hw[2] | ((uint32_t)hw[3] << 16);
        lo2.x = (uint32_t)lw[0] | ((uint32_t)lw[1] << 16);
        lo2.y = (uint32_t)lw[2] | ((uint32_t)lw[3] << 16);
        ((uint2*)hi)[i] = ho;
        ((uint2*)lo)[i] = lo2;
    }
}

// ---------------------------------------------------------------------------
// mma.sync m16n8k16 bf16 + ldmatrix helpers (compute_100-legal).
// ---------------------------------------------------------------------------
__device__ __forceinline__ void mma16816(float* c, const uint32_t* a,
                                         const uint32_t* b) {
    asm volatile(
        "mma.sync.aligned.m16n8k16.row.col.f32.bf16.bf16.f32 "
        "{%0,%1,%2,%3}, {%4,%5,%6,%7}, {%8,%9}, {%0,%1,%2,%3};"
        : "+f"(c[0]), "+f"(c[1]), "+f"(c[2]), "+f"(c[3])
        : "r"(a[0]), "r"(a[1]), "r"(a[2]), "r"(a[3]), "r"(b[0]), "r"(b[1]));
}
__device__ __forceinline__ void ldsm_x4(uint32_t& r0, uint32_t& r1,
                                        uint32_t& r2, uint32_t& r3,
                                        uint32_t addr) {
    asm volatile("ldmatrix.sync.aligned.m8n8.x4.shared.b16 {%0,%1,%2,%3}, [%4];"
                 : "=r"(r0), "=r"(r1), "=r"(r2), "=r"(r3) : "r"(addr));
}
__device__ __forceinline__ uint32_t sm_u32(const void* p) {
    return (uint32_t)__cvta_generic_to_shared(p);
}

// ============================ PHASE 1 =======================================
#define KT   64
#define SROW 72
#define TILE_ELE (128 * SROW)

__global__ void __launch_bounds__(256, 2)
ih_mma_kernel(const float* __restrict__ bih) {
    extern __shared__ __nv_bfloat16 smem[];
    __nv_bfloat16* SAH = smem;
    __nv_bfloat16* SAL = smem + TILE_ELE;
    __nv_bfloat16* SBH = smem + 2 * TILE_ELE;
    __nv_bfloat16* SBL = smem + 3 * TILE_ELE;

    const int mt  = blockIdx.x;
    const int gt  = blockIdx.y;
    const int n   = blockIdx.z;
    const int tid = threadIdx.x;
    const int wid = tid >> 5;
    const int lane = tid & 31;
    const int wm  = wid & 1;
    const int wn  = wid >> 1;
    const int g   = lane >> 2;
    const int tig = lane & 3;

    const __nv_bfloat16* axh = g_xhi + ((size_t)(mt * N_ + n)) * T_ * I_;
    const __nv_bfloat16* axl = g_xlo + ((size_t)(mt * N_ + n)) * T_ * I_;
    const __nv_bfloat16* bwh = g_whi + ((size_t)(n * G3 + gt * 128)) * I_;
    const __nv_bfloat16* bwl = g_wlo + ((size_t)(n * G3 + gt * 128)) * I_;

    // ldmatrix lane addressing.
    // A x4 tiles: (rows0-7,k0)(rows8-15,k0)(rows0-7,k8)(rows8-15,k8)
    const int arow  = wm * 64 + (lane & 15);
    const int akoff = (lane >> 4) * 8;
    uint32_t aAH[4], aAL[4];
#pragma unroll
    for (int mi = 0; mi < 4; mi++) {
        aAH[mi] = sm_u32(SAH + (arow + mi * 16) * SROW + akoff);
        aAL[mi] = sm_u32(SAL + (arow + mi * 16) * SROW + akoff);
    }
    // B x4 pairing of two n8k16 frags: lanes 0-7 (nbP,k0), 8-15 (nbP,k8),
    // 16-23 (nbQ,k0), 24-31 (nbQ,k8).
    const int bkoff = ((lane >> 3) & 1) * 8;
    const int bhalf = lane >> 4;           // 0: first frag, 1: second frag
    const int brow  = lane & 7;
    const int nb0 = wn * 32 + brow;        // frag ni rows: wn*32 + ni*8 + brow
    uint32_t aB01h = sm_u32(SBH + (nb0 + (bhalf ? 8 : 0)) * SROW + bkoff);
    uint32_t aB23h = sm_u32(SBH + (nb0 + (bhalf ? 24 : 16)) * SROW + bkoff);
    uint32_t aB01l = sm_u32(SBL + (nb0 + (bhalf ? 8 : 0)) * SROW + bkoff);
    uint32_t aB23l = sm_u32(SBL + (nb0 + (bhalf ? 24 : 16)) * SROW + bkoff);

    float acc[4][4][4];
#pragma unroll
    for (int mi = 0; mi < 4; mi++)
#pragma unroll
        for (int ni = 0; ni < 4; ni++)
#pragma unroll
            for (int u = 0; u < 4; u++) acc[mi][ni][u] = 0.0f;

    for (int kt = 0; kt < I_; kt += KT) {
#pragma unroll
        for (int l = 0; l < 4; l++) {
            int it = tid + (l << 8);
            int r = it >> 3;
            int q = it & 7;
            size_t goff = (size_t)r * I_ + kt + q * 8;
            int soff = r * SROW + q * 8;
            *(uint4*)(SAH + soff) = *(const uint4*)(axh + goff);
            *(uint4*)(SAL + soff) = *(const uint4*)(axl + goff);
            *(uint4*)(SBH + soff) = *(const uint4*)(bwh + goff);
            *(uint4*)(SBL + soff) = *(const uint4*)(bwl + goff);
        }
        __syncthreads();

#pragma unroll
        for (int kk = 0; kk < KT; kk += 16) {
            const uint32_t off = kk * 2;   // bytes
            uint32_t af[4][4], bh[4][2], bl[4][2];
#pragma unroll
            for (int mi = 0; mi < 4; mi++)
                ldsm_x4(af[mi][0], af[mi][1], af[mi][2], af[mi][3], aAH[mi] + off);
            ldsm_x4(bh[0][0], bh[0][1], bh[1][0], bh[1][1], aB01h + off);
            ldsm_x4(bh[2][0], bh[2][1], bh[3][0], bh[3][1], aB23h + off);
            ldsm_x4(bl[0][0], bl[0][1], bl[1][0], bl[1][1], aB01l + off);
            ldsm_x4(bl[2][0], bl[2][1], bl[3][0], bl[3][1], aB23l + off);
#pragma unroll
            for (int mi = 0; mi < 4; mi++)
#pragma unroll
                for (int ni = 0; ni < 4; ni++) {
                    mma16816(acc[mi][ni], af[mi], bh[ni]);
                    mma16816(acc[mi][ni], af[mi], bl[ni]);
                }
#pragma unroll
            for (int mi = 0; mi < 4; mi++)
                ldsm_x4(af[mi][0], af[mi][1], af[mi][2], af[mi][3], aAL[mi] + off);
#pragma unroll
            for (int mi = 0; mi < 4; mi++)
#pragma unroll
                for (int ni = 0; ni < 4; ni++)
                    mma16816(acc[mi][ni], af[mi], bh[ni]);
        }
        __syncthreads();
    }

#pragma unroll
    for (int ni = 0; ni < 4; ni++) {
        const int col = gt * 128 + wn * 32 + ni * 8 + 2 * tig;
        const float2 bias = *(const float2*)(bih + n * G3 + col);
#pragma unroll
        for (int mi = 0; mi < 4; mi++) {
            int row = wm * 64 + mi * 16 + g;
            float2 o0, o1;
            o0.x = acc[mi][ni][0] + bias.x;
            o0.y = acc[mi][ni][1] + bias.y;
            o1.x = acc[mi][ni][2] + bias.x;
            o1.y = acc[mi][ni][3] + bias.y;
            *(float2*)(g_IH + (((size_t)(n * T_ + row)) * B_ + mt) * G3 + col) = o0;
            *(float2*)(g_IH + (((size_t)(n * T_ + row + 8)) * B_ + mt) * G3 + col) = o1;
        }
    }
}

// ============================ PHASE 2 =======================================
#define WPAD 264

__global__ void __launch_bounds__(256, 1)
gru_mma_kernel(const float* __restrict__ whh,
               const float* __restrict__ bhh,
               float* __restrict__ out) {
    extern __shared__ __nv_bfloat16 sm2[];
    __nv_bfloat16* wsh = sm2;                 // [96][WPAD]
    __nv_bfloat16* wsl = wsh + 96 * WPAD;
    __nv_bfloat16* hsh = wsl + 96 * WPAD;     // [64][WPAD]
    __nv_bfloat16* hsl = hsh + 64 * WPAD;

    const int n    = blockIdx.y;
    const int jc   = blockIdx.x;
    const int tid  = threadIdx.x;
    const int wid  = tid >> 5;
    const int lane = tid & 31;
    const int wm   = wid & 1;
    const int wn   = wid >> 1;
    const int tig  = lane & 3;

    // Convert Whh slice fp32 -> hi/lo bf16 smem (once).
    for (int it = tid; it < 96 * 64; it += 256) {
        int row  = it >> 6;
        int q    = it & 63;
        int gate = row >> 5;
        int jl   = row & 31;
        const float4 wv = *(const float4*)(whh +
            ((size_t)(n * G3 + gate * H_ + jc * 32 + jl)) * H_ + q * 4);
        float v[4] = {wv.x, wv.y, wv.z, wv.w};
        uint32_t hw[2], lw[2];
#pragma unroll
        for (int u = 0; u < 2; u++) {
            __nv_bfloat16 h0 = __float2bfloat16_rn(v[2 * u]);
            __nv_bfloat16 h1 = __float2bfloat16_rn(v[2 * u + 1]);
            float r0 = v[2 * u]     - __bfloat162float(h0);
            float r1 = v[2 * u + 1] - __bfloat162float(h1);
            hw[u] = (uint32_t)__bfloat16_as_ushort(h0) |
                    ((uint32_t)__bfloat16_as_ushort(h1) << 16);
            lw[u] = (uint32_t)__bfloat16_as_ushort(__float2bfloat16_rn(r0)) |
                    ((uint32_t)__bfloat16_as_ushort(__float2bfloat16_rn(r1)) << 16);
        }
        *(uint2*)(wsh + row * WPAD + q * 4) = make_uint2(hw[0], hw[1]);
        *(uint2*)(wsl + row * WPAD + q * 4) = make_uint2(lw[0], lw[1]);
    }

    // ldmatrix lane bases.
    const int arow  = wm * 32 + (lane & 15);
    const int akoff = (lane >> 4) * 8;
    uint32_t aAh[2], aAl[2];
#pragma unroll
    for (int mi = 0; mi < 2; mi++) {
        aAh[mi] = sm_u32(hsh + (arow + mi * 16) * WPAD + akoff);
        aAl[mi] = sm_u32(hsl + (arow + mi * 16) * WPAD + akoff);
    }
    // B frags: rows nb(ni) = ni*32 + wn*8. Pairs: (hi0,hi1), (hi2,lo0), (lo1,lo2).
    const int bkoff = ((lane >> 3) & 1) * 8;
    const int bhalf = lane >> 4;
    const int brow  = wn * 8 + (lane & 7);
    uint32_t aBP0 = sm_u32(wsh + (brow + (bhalf ? 32 : 0)) * WPAD + bkoff);
    uint32_t aBP1 = bhalf ? sm_u32(wsl + brow * WPAD + bkoff)
                          : sm_u32(wsh + (brow + 64) * WPAD + bkoff);
    uint32_t aBP2 = sm_u32(wsl + (brow + (bhalf ? 64 : 32)) * WPAD + bkoff);

    const int jg0 = jc * 32 + wn * 8 + 2 * tig;
    const float2 bhr2 = *(const float2*)(bhh + n * G3 + jg0);
    const float2 bhz2 = *(const float2*)(bhh + n * G3 + H_ + jg0);
    const float2 bhn2 = *(const float2*)(bhh + n * G3 + 2 * H_ + jg0);

    for (int t = 0; t < T_; t++) {
        const __nv_bfloat16* hhsrc = g_hhi + ((size_t)((t & 1) * N_ + n)) * B_ * H_;
        const __nv_bfloat16* hlsrc = g_hlo + ((size_t)((t & 1) * N_ + n)) * B_ * H_;
        __syncthreads();
        for (int it = tid; it < 2048; it += 256) {
            int r = it >> 5, q = it & 31;
            *(uint4*)(hsh + r * WPAD + q * 8) =
                __ldcg((const uint4*)(hhsrc + r * H_ + q * 8));
            *(uint4*)(hsl + r * WPAD + q * 8) =
                __ldcg((const uint4*)(hlsrc + r * H_ + q * 8));
        }
        __syncthreads();

        float acc[2][3][4];
#pragma unroll
        for (int mi = 0; mi < 2; mi++)
#pragma unroll
            for (int ni = 0; ni < 3; ni++)
#pragma unroll
                for (int u = 0; u < 4; u++) acc[mi][ni][u] = 0.0f;

#pragma unroll
        for (int kk = 0; kk < H_; kk += 16) {
            const uint32_t off = kk * 2;
            uint32_t ah[2][4], al[2][4], bh[3][2], bl[3][2];
#pragma unroll
            for (int mi = 0; mi < 2; mi++) {
                ldsm_x4(ah[mi][0], ah[mi][1], ah[mi][2], ah[mi][3], aAh[mi] + off);
                ldsm_x4(al[mi][0], al[mi][1], al[mi][2], al[mi][3], aAl[mi] + off);
            }
            ldsm_x4(bh[0][0], bh[0][1], bh[1][0], bh[1][1], aBP0 + off);
            ldsm_x4(bh[2][0], bh[2][1], bl[0][0], bl[0][1], aBP1 + off);
            ldsm_x4(bl[1][0], bl[1][1], bl[2][0], bl[2][1], aBP2 + off);
#pragma unroll
            for (int mi = 0; mi < 2; mi++)
#pragma unroll
                for (int ni = 0; ni < 3; ni++) {
                    mma16816(acc[mi][ni], ah[mi], bh[ni]);
                    mma16816(acc[mi][ni], ah[mi], bl[ni]);
                    mma16816(acc[mi][ni], al[mi], bh[ni]);
                }
        }

        // Fused gate epilogue.
        const float* ihb = g_IH + ((size_t)(n * T_ + t) * B_) * G3;
        const int buf = (t + 1) & 1;
        __nv_bfloat16* hhdst = g_hhi + ((size_t)(buf * N_ + n)) * B_ * H_;
        __nv_bfloat16* hldst = g_hlo + ((size_t)(buf * N_ + n)) * B_ * H_;
        const int g8 = lane >> 2;

#pragma unroll
        for (int mi = 0; mi < 2; mi++)
#pragma unroll
            for (int rr = 0; rr < 2; rr++) {
                const int b  = wm * 32 + mi * 16 + g8 + rr * 8;
                const int ci = rr * 2;
                float2 ihr = *(const float2*)(ihb + (size_t)b * G3 + jg0);
                float2 ihz = *(const float2*)(ihb + (size_t)b * G3 + H_ + jg0);
                float2 ihn = *(const float2*)(ihb + (size_t)b * G3 + 2 * H_ + jg0);
                float hp0 = __bfloat162float(hsh[b * WPAD + jg0]) +
                            __bfloat162float(hsl[b * WPAD + jg0]);
                float hp1 = __bfloat162float(hsh[b * WPAD + jg0 + 1]) +
                            __bfloat162float(hsl[b * WPAD + jg0 + 1]);
                float hr0 = acc[mi][0][ci]     + bhr2.x;
                float hr1 = acc[mi][0][ci + 1] + bhr2.y;
                float hz0 = acc[mi][1][ci]     + bhz2.x;
                float hz1 = acc[mi][1][ci + 1] + bhz2.y;
                float hn0 = acc[mi][2][ci]     + bhn2.x;
                float hn1 = acc[mi][2][ci + 1] + bhn2.y;
                float rg0 = 1.0f / (1.0f + __expf(-(ihr.x + hr0)));
                float rg1 = 1.0f / (1.0f + __expf(-(ihr.y + hr1)));
                float zg0 = 1.0f / (1.0f + __expf(-(ihz.x + hz0)));
                float zg1 = 1.0f / (1.0f + __expf(-(ihz.y + hz1)));
                float ng0 = tanhf(ihn.x + rg0 * hn0);
                float ng1 = tanhf(ihn.y + rg1 * hn1);
                float h0 = (1.0f - zg0) * ng0 + zg0 * hp0;
                float h1 = (1.0f - zg1) * ng1 + zg1 * hp1;

                float2 o; o.x = h0; o.y = h1;
                *(float2*)(out + ((size_t)(b * N_ + n) * T_ + t) * H_ + jg0) = o;

                __nv_bfloat16 hi0 = __float2bfloat16_rn(h0);
                __nv_bfloat16 hi1 = __float2bfloat16_rn(h1);
                __nv_bfloat16 lo0 = __float2bfloat16_rn(h0 - __bfloat162float(hi0));
                __nv_bfloat16 lo1 = __float2bfloat16_rn(h1 - __bfloat162float(hi1));
                *(uint32_t*)(hhdst + (size_t)b * H_ + jg0) =
                    (uint32_t)__bfloat16_as_ushort(hi0) |
                    ((uint32_t)__bfloat16_as_ushort(hi1) << 16);
                *(uint32_t*)(hldst + (size_t)b * H_ + jg0) =
                    (uint32_t)__bfloat16_as_ushort(lo0) |
                    ((uint32_t)__bfloat16_as_ushort(lo1) << 16);
            }

        // Grid barrier.
        __threadfence();
        __syncthreads();
        if (tid == 0) {
            int target = t + 1;
            int old = atomicAdd(&g_bar_count, 1);
            if (old == NCTA - 1) {
                g_bar_count = 0;
                __threadfence();
                g_bar_gen = target;
            } else {
                while (g_bar_gen < target) __nanosleep(32);
            }
        }
        __syncthreads();
    }
}

// ---------------------------------------------------------------------------
extern "C" void kernel_launch(void* const* d_in, const int* in_sizes, int n_in,
                              void* d_out, int out_size) {
    const float* x   = (const float*)d_in[0];
    const float* wih = (const float*)d_in[1];
    const float* whh = (const float*)d_in[2];
    const float* bih = (const float*)d_in[3];
    const float* bhh = (const float*)d_in[4];
    float* out = (float*)d_out;

    const int smem1 = 4 * TILE_ELE * (int)sizeof(__nv_bfloat16);       // 73,728 B
    const int smem2 = (2 * 96 * WPAD + 2 * 64 * WPAD) *
                      (int)sizeof(__nv_bfloat16);                      // 168,960 B
    cudaFuncSetAttribute(ih_mma_kernel,
                         cudaFuncAttributeMaxDynamicSharedMemorySize, smem1);
    cudaFuncSetAttribute(gru_mma_kernel,
                         cudaFuncAttributeMaxDynamicSharedMemorySize, smem2);

    zero_kernel<<<256, 256>>>();

    const size_t nx4 = (size_t)B_ * N_ * T_ * I_ / 4;
    const size_t nw4 = (size_t)N_ * G3 * I_ / 4;
    cvt_hilo_kernel<<<4096, 256>>>(x, 0, nx4);
    cvt_hilo_kernel<<<1024, 256>>>(wih, 1, nw4);

    ih_mma_kernel<<<dim3(64, 6, 16), 256, smem1>>>(bih);
    gru_mma_kernel<<<dim3(8, 16), 256, smem2>>>(whh, bhh, out);
}

// round 13
// speedup vs baseline: 2.5922x; 1.2136x over previous
#include <cuda_runtime.h>
#include <cuda_bf16.h>
#include <cstdint>

#define B_  64
#define N_  16
#define T_  128
#define I_  256
#define H_  256
#define G3  768    // 3*H

// Scratch: input projection IH[n][t][b][g] (bih folded in), fp32.
__device__ float g_IH[(size_t)N_ * T_ * B_ * G3];
// hi/lo bf16 copies of x and wih (phase 1).
__device__ __nv_bfloat16 g_xhi[(size_t)B_ * N_ * T_ * I_];
__device__ __nv_bfloat16 g_xlo[(size_t)B_ * N_ * T_ * I_];
__device__ __nv_bfloat16 g_whi[(size_t)N_ * G3 * I_];
__device__ __nv_bfloat16 g_wlo[(size_t)N_ * G3 * I_];
// Double-buffered hidden state as hi/lo bf16 pairs: [2][n][b][k].
__device__ __nv_bfloat16 g_hhi[2 * N_ * B_ * H_];
__device__ __nv_bfloat16 g_hlo[2 * N_ * B_ * H_];
// Per-n software barriers (8 CTAs each), reset per launch by zero_kernel.
__device__ int g_bar_cnt[N_];
__device__ volatile int g_bar_gen[N_];

// ---------------------------------------------------------------------------
__global__ void zero_kernel() {
    int i = blockIdx.x * blockDim.x + threadIdx.x;
    if (i < 65536) {
        ((uint4*)g_hhi)[i] = make_uint4(0, 0, 0, 0);
        ((uint4*)g_hlo)[i] = make_uint4(0, 0, 0, 0);
    }
    if (i < N_) { g_bar_cnt[i] = 0; g_bar_gen[i] = 0; }
}

// ---------------------------------------------------------------------------
// fp32 -> (hi, lo) bf16 split, writing directly to device globals.
// ---------------------------------------------------------------------------
__global__ void cvt_hilo_kernel(const float* __restrict__ src,
                                int which, size_t n4) {
    __nv_bfloat16* hi = which ? g_whi : g_xhi;
    __nv_bfloat16* lo = which ? g_wlo : g_xlo;
    for (size_t i = blockIdx.x * (size_t)blockDim.x + threadIdx.x; i < n4;
         i += (size_t)gridDim.x * blockDim.x) {
        float4 v = ((const float4*)src)[i];
        float vv[4] = {v.x, v.y, v.z, v.w};
        uint16_t hw[4], lw[4];
#pragma unroll
        for (int u = 0; u < 4; u++) {
            __nv_bfloat16 h = __float2bfloat16_rn(vv[u]);
            float r = vv[u] - __bfloat162float(h);
            __nv_bfloat16 l = __float2bfloat16_rn(r);
            hw[u] = __bfloat16_as_ushort(h);
            lw[u] = __bfloat16_as_ushort(l);
        }
        uint2 ho, lo2;
        ho.x  = (uint32_t)hw[0] | ((uint32_t)hw[1] << 16);
        ho.y  = (uint32_t)hw[2] | ((uint32_t)hw[3] << 16);
        lo2.x = (uint32_t)lw[0] | ((uint32_t)lw[1] << 16);
        lo2.y = (uint32_t)lw[2] | ((uint32_t)lw[3] << 16);
        ((uint2*)hi)[i] = ho;
        ((uint2*)lo)[i] = lo2;
    }
}

// ---------------------------------------------------------------------------
// mma.sync m16n8k16 bf16 + ldmatrix helpers (compute_100-legal).
// ---------------------------------------------------------------------------
__device__ __forceinline__ void mma16816(float* c, const uint32_t* a,
                                         const uint32_t* b) {
    asm volatile(
        "mma.sync.aligned.m16n8k16.row.col.f32.bf16.bf16.f32 "
        "{%0,%1,%2,%3}, {%4,%5,%6,%7}, {%8,%9}, {%0,%1,%2,%3};"
        : "+f"(c[0]), "+f"(c[1]), "+f"(c[2]), "+f"(c[3])
        : "r"(a[0]), "r"(a[1]), "r"(a[2]), "r"(a[3]), "r"(b[0]), "r"(b[1]));
}
__device__ __forceinline__ void ldsm_x4(uint32_t& r0, uint32_t& r1,
                                        uint32_t& r2, uint32_t& r3,
                                        uint32_t addr) {
    asm volatile("ldmatrix.sync.aligned.m8n8.x4.shared.b16 {%0,%1,%2,%3}, [%4];"
                 : "=r"(r0), "=r"(r1), "=r"(r2), "=r"(r3) : "r"(addr));
}
__device__ __forceinline__ uint32_t sm_u32(const void* p) {
    return (uint32_t)__cvta_generic_to_shared(p);
}

// ============================ PHASE 1 (unchanged, validated) ================
#define KT   64
#define SROW 72
#define TILE_ELE (128 * SROW)

__global__ void __launch_bounds__(256, 2)
ih_mma_kernel(const float* __restrict__ bih) {
    extern __shared__ __nv_bfloat16 smem[];
    __nv_bfloat16* SAH = smem;
    __nv_bfloat16* SAL = smem + TILE_ELE;
    __nv_bfloat16* SBH = smem + 2 * TILE_ELE;
    __nv_bfloat16* SBL = smem + 3 * TILE_ELE;

    const int mt  = blockIdx.x;
    const int gt  = blockIdx.y;
    const int n   = blockIdx.z;
    const int tid = threadIdx.x;
    const int wid = tid >> 5;
    const int lane = tid & 31;
    const int wm  = wid & 1;
    const int wn  = wid >> 1;
    const int g   = lane >> 2;
    const int tig = lane & 3;

    const __nv_bfloat16* axh = g_xhi + ((size_t)(mt * N_ + n)) * T_ * I_;
    const __nv_bfloat16* axl = g_xlo + ((size_t)(mt * N_ + n)) * T_ * I_;
    const __nv_bfloat16* bwh = g_whi + ((size_t)(n * G3 + gt * 128)) * I_;
    const __nv_bfloat16* bwl = g_wlo + ((size_t)(n * G3 + gt * 128)) * I_;

    const int arow  = wm * 64 + (lane & 15);
    const int akoff = (lane >> 4) * 8;
    uint32_t aAH[4], aAL[4];
#pragma unroll
    for (int mi = 0; mi < 4; mi++) {
        aAH[mi] = sm_u32(SAH + (arow + mi * 16) * SROW + akoff);
        aAL[mi] = sm_u32(SAL + (arow + mi * 16) * SROW + akoff);
    }
    const int bkoff = ((lane >> 3) & 1) * 8;
    const int bhalf = lane >> 4;
    const int brow  = lane & 7;
    const int nb0 = wn * 32 + brow;
    uint32_t aB01h = sm_u32(SBH + (nb0 + (bhalf ? 8 : 0)) * SROW + bkoff);
    uint32_t aB23h = sm_u32(SBH + (nb0 + (bhalf ? 24 : 16)) * SROW + bkoff);
    uint32_t aB01l = sm_u32(SBL + (nb0 + (bhalf ? 8 : 0)) * SROW + bkoff);
    uint32_t aB23l = sm_u32(SBL + (nb0 + (bhalf ? 24 : 16)) * SROW + bkoff);

    float acc[4][4][4];
#pragma unroll
    for (int mi = 0; mi < 4; mi++)
#pragma unroll
        for (int ni = 0; ni < 4; ni++)
#pragma unroll
            for (int u = 0; u < 4; u++) acc[mi][ni][u] = 0.0f;

    for (int kt = 0; kt < I_; kt += KT) {
#pragma unroll
        for (int l = 0; l < 4; l++) {
            int it = tid + (l << 8);
            int r = it >> 3;
            int q = it & 7;
            size_t goff = (size_t)r * I_ + kt + q * 8;
            int soff = r * SROW + q * 8;
            *(uint4*)(SAH + soff) = *(const uint4*)(axh + goff);
            *(uint4*)(SAL + soff) = *(const uint4*)(axl + goff);
            *(uint4*)(SBH + soff) = *(const uint4*)(bwh + goff);
            *(uint4*)(SBL + soff) = *(const uint4*)(bwl + goff);
        }
        __syncthreads();

#pragma unroll
        for (int kk = 0; kk < KT; kk += 16) {
            const uint32_t off = kk * 2;
            uint32_t af[4][4], bh[4][2], bl[4][2];
#pragma unroll
            for (int mi = 0; mi < 4; mi++)
                ldsm_x4(af[mi][0], af[mi][1], af[mi][2], af[mi][3], aAH[mi] + off);
            ldsm_x4(bh[0][0], bh[0][1], bh[1][0], bh[1][1], aB01h + off);
            ldsm_x4(bh[2][0], bh[2][1], bh[3][0], bh[3][1], aB23h + off);
            ldsm_x4(bl[0][0], bl[0][1], bl[1][0], bl[1][1], aB01l + off);
            ldsm_x4(bl[2][0], bl[2][1], bl[3][0], bl[3][1], aB23l + off);
#pragma unroll
            for (int mi = 0; mi < 4; mi++)
#pragma unroll
                for (int ni = 0; ni < 4; ni++) {
                    mma16816(acc[mi][ni], af[mi], bh[ni]);
                    mma16816(acc[mi][ni], af[mi], bl[ni]);
                }
#pragma unroll
            for (int mi = 0; mi < 4; mi++)
                ldsm_x4(af[mi][0], af[mi][1], af[mi][2], af[mi][3], aAL[mi] + off);
#pragma unroll
            for (int mi = 0; mi < 4; mi++)
#pragma unroll
                for (int ni = 0; ni < 4; ni++)
                    mma16816(acc[mi][ni], af[mi], bh[ni]);
        }
        __syncthreads();
    }

#pragma unroll
    for (int ni = 0; ni < 4; ni++) {
        const int col = gt * 128 + wn * 32 + ni * 8 + 2 * tig;
        const float2 bias = *(const float2*)(bih + n * G3 + col);
#pragma unroll
        for (int mi = 0; mi < 4; mi++) {
            int row = wm * 64 + mi * 16 + g;
            float2 o0, o1;
            o0.x = acc[mi][ni][0] + bias.x;
            o0.y = acc[mi][ni][1] + bias.y;
            o1.x = acc[mi][ni][2] + bias.x;
            o1.y = acc[mi][ni][3] + bias.y;
            *(float2*)(g_IH + (((size_t)(n * T_ + row)) * B_ + mt) * G3 + col) = o0;
            *(float2*)(g_IH + (((size_t)(n * T_ + row + 8)) * B_ + mt) * G3 + col) = o1;
        }
    }
}

// ============================ PHASE 2 =======================================
// Changes vs R10: h_prev carried in registers (no epilogue smem reads, one
// less __syncthreads), IH gate inputs prefetched into registers before the
// MMA loop, and a per-n 8-CTA barrier (16 independent slots, no nanosleep).
// ---------------------------------------------------------------------------
#define WPAD 264

__global__ void __launch_bounds__(256, 1)
gru_mma_kernel(const float* __restrict__ whh,
               const float* __restrict__ bhh,
               float* __restrict__ out) {
    extern __shared__ __nv_bfloat16 sm2[];
    __nv_bfloat16* wsh = sm2;                 // [96][WPAD]
    __nv_bfloat16* wsl = wsh + 96 * WPAD;
    __nv_bfloat16* hsh = wsl + 96 * WPAD;     // [64][WPAD]
    __nv_bfloat16* hsl = hsh + 64 * WPAD;

    const int n    = blockIdx.y;
    const int jc   = blockIdx.x;
    const int tid  = threadIdx.x;
    const int wid  = tid >> 5;
    const int lane = tid & 31;
    const int wm   = wid & 1;
    const int wn   = wid >> 1;
    const int tig  = lane & 3;
    const int g8   = lane >> 2;

    // Convert Whh slice fp32 -> hi/lo bf16 smem (once).
    for (int it = tid; it < 96 * 64; it += 256) {
        int row  = it >> 6;
        int q    = it & 63;
        int gate = row >> 5;
        int jl   = row & 31;
        const float4 wv = *(const float4*)(whh +
            ((size_t)(n * G3 + gate * H_ + jc * 32 + jl)) * H_ + q * 4);
        float v[4] = {wv.x, wv.y, wv.z, wv.w};
        uint32_t hw[2], lw[2];
#pragma unroll
        for (int u = 0; u < 2; u++) {
            __nv_bfloat16 h0 = __float2bfloat16_rn(v[2 * u]);
            __nv_bfloat16 h1 = __float2bfloat16_rn(v[2 * u + 1]);
            float r0 = v[2 * u]     - __bfloat162float(h0);
            float r1 = v[2 * u + 1] - __bfloat162float(h1);
            hw[u] = (uint32_t)__bfloat16_as_ushort(h0) |
                    ((uint32_t)__bfloat16_as_ushort(h1) << 16);
            lw[u] = (uint32_t)__bfloat16_as_ushort(__float2bfloat16_rn(r0)) |
                    ((uint32_t)__bfloat16_as_ushort(__float2bfloat16_rn(r1)) << 16);
        }
        *(uint2*)(wsh + row * WPAD + q * 4) = make_uint2(hw[0], hw[1]);
        *(uint2*)(wsl + row * WPAD + q * 4) = make_uint2(lw[0], lw[1]);
    }

    // ldmatrix lane bases.
    const int arow  = wm * 32 + (lane & 15);
    const int akoff = (lane >> 4) * 8;
    uint32_t aAh[2], aAl[2];
#pragma unroll
    for (int mi = 0; mi < 2; mi++) {
        aAh[mi] = sm_u32(hsh + (arow + mi * 16) * WPAD + akoff);
        aAl[mi] = sm_u32(hsl + (arow + mi * 16) * WPAD + akoff);
    }
    const int bkoff = ((lane >> 3) & 1) * 8;
    const int bhalf = lane >> 4;
    const int brow  = wn * 8 + (lane & 7);
    uint32_t aBP0 = sm_u32(wsh + (brow + (bhalf ? 32 : 0)) * WPAD + bkoff);
    uint32_t aBP1 = bhalf ? sm_u32(wsl + brow * WPAD + bkoff)
                          : sm_u32(wsh + (brow + 64) * WPAD + bkoff);
    uint32_t aBP2 = sm_u32(wsl + (brow + (bhalf ? 64 : 32)) * WPAD + bkoff);

    const int jg0 = jc * 32 + wn * 8 + 2 * tig;
    const float2 bhr2 = *(const float2*)(bhh + n * G3 + jg0);
    const float2 bhz2 = *(const float2*)(bhh + n * G3 + H_ + jg0);
    const float2 bhn2 = *(const float2*)(bhh + n * G3 + 2 * H_ + jg0);

    // h_prev carried in registers: idx = mi*2 + rr -> (b, jg0..jg0+1).
    float2 hpr[4];
#pragma unroll
    for (int i = 0; i < 4; i++) { hpr[i].x = 0.0f; hpr[i].y = 0.0f; }

    for (int t = 0; t < T_; t++) {
        // Stage h (hi/lo bf16) from gmem (L2-coherent loads).
        const __nv_bfloat16* hhsrc = g_hhi + ((size_t)((t & 1) * N_ + n)) * B_ * H_;
        const __nv_bfloat16* hlsrc = g_hlo + ((size_t)((t & 1) * N_ + n)) * B_ * H_;
        for (int it = tid; it < 2048; it += 256) {
            int r = it >> 5, q = it & 31;
            *(uint4*)(hsh + r * WPAD + q * 8) =
                __ldcg((const uint4*)(hhsrc + r * H_ + q * 8));
            *(uint4*)(hsl + r * WPAD + q * 8) =
                __ldcg((const uint4*)(hlsrc + r * H_ + q * 8));
        }

        // Prefetch IH gate inputs (independent of h) into registers.
        const float* ihb = g_IH + ((size_t)(n * T_ + t) * B_) * G3;
        float2 pir[4], piz[4], pin[4];
#pragma unroll
        for (int mi = 0; mi < 2; mi++)
#pragma unroll
            for (int rr = 0; rr < 2; rr++) {
                const int b = wm * 32 + mi * 16 + g8 + rr * 8;
                const int idx = mi * 2 + rr;
                pir[idx] = *(const float2*)(ihb + (size_t)b * G3 + jg0);
                piz[idx] = *(const float2*)(ihb + (size_t)b * G3 + H_ + jg0);
                pin[idx] = *(const float2*)(ihb + (size_t)b * G3 + 2 * H_ + jg0);
            }
        __syncthreads();

        float acc[2][3][4];
#pragma unroll
        for (int mi = 0; mi < 2; mi++)
#pragma unroll
            for (int ni = 0; ni < 3; ni++)
#pragma unroll
                for (int u = 0; u < 4; u++) acc[mi][ni][u] = 0.0f;

#pragma unroll
        for (int kk = 0; kk < H_; kk += 16) {
            const uint32_t off = kk * 2;
            uint32_t ah[2][4], al[2][4], bh[3][2], bl[3][2];
#pragma unroll
            for (int mi = 0; mi < 2; mi++) {
                ldsm_x4(ah[mi][0], ah[mi][1], ah[mi][2], ah[mi][3], aAh[mi] + off);
                ldsm_x4(al[mi][0], al[mi][1], al[mi][2], al[mi][3], aAl[mi] + off);
            }
            ldsm_x4(bh[0][0], bh[0][1], bh[1][0], bh[1][1], aBP0 + off);
            ldsm_x4(bh[2][0], bh[2][1], bl[0][0], bl[0][1], aBP1 + off);
            ldsm_x4(bl[1][0], bl[1][1], bl[2][0], bl[2][1], aBP2 + off);
#pragma unroll
            for (int mi = 0; mi < 2; mi++)
#pragma unroll
                for (int ni = 0; ni < 3; ni++) {
                    mma16816(acc[mi][ni], ah[mi], bh[ni]);
                    mma16816(acc[mi][ni], ah[mi], bl[ni]);
                    mma16816(acc[mi][ni], al[mi], bh[ni]);
                }
        }

        // Fused gate epilogue (h_prev and IH already in registers).
        const int buf = (t + 1) & 1;
        __nv_bfloat16* hhdst = g_hhi + ((size_t)(buf * N_ + n)) * B_ * H_;
        __nv_bfloat16* hldst = g_hlo + ((size_t)(buf * N_ + n)) * B_ * H_;

#pragma unroll
        for (int mi = 0; mi < 2; mi++)
#pragma unroll
            for (int rr = 0; rr < 2; rr++) {
                const int b   = wm * 32 + mi * 16 + g8 + rr * 8;
                const int ci  = rr * 2;
                const int idx = mi * 2 + rr;
                float hr0 = acc[mi][0][ci]     + bhr2.x;
                float hr1 = acc[mi][0][ci + 1] + bhr2.y;
                float hz0 = acc[mi][1][ci]     + bhz2.x;
                float hz1 = acc[mi][1][ci + 1] + bhz2.y;
                float hn0 = acc[mi][2][ci]     + bhn2.x;
                float hn1 = acc[mi][2][ci + 1] + bhn2.y;
                float rg0 = 1.0f / (1.0f + __expf(-(pir[idx].x + hr0)));
                float rg1 = 1.0f / (1.0f + __expf(-(pir[idx].y + hr1)));
                float zg0 = 1.0f / (1.0f + __expf(-(piz[idx].x + hz0)));
                float zg1 = 1.0f / (1.0f + __expf(-(piz[idx].y + hz1)));
                float ng0 = tanhf(pin[idx].x + rg0 * hn0);
                float ng1 = tanhf(pin[idx].y + rg1 * hn1);
                float h0 = (1.0f - zg0) * ng0 + zg0 * hpr[idx].x;
                float h1 = (1.0f - zg1) * ng1 + zg1 * hpr[idx].y;
                hpr[idx].x = h0;
                hpr[idx].y = h1;

                float2 o; o.x = h0; o.y = h1;
                *(float2*)(out + ((size_t)(b * N_ + n) * T_ + t) * H_ + jg0) = o;

                __nv_bfloat16 hi0 = __float2bfloat16_rn(h0);
                __nv_bfloat16 hi1 = __float2bfloat16_rn(h1);
                __nv_bfloat16 lo0 = __float2bfloat16_rn(h0 - __bfloat162float(hi0));
                __nv_bfloat16 lo1 = __float2bfloat16_rn(h1 - __bfloat162float(hi1));
                *(uint32_t*)(hhdst + (size_t)b * H_ + jg0) =
                    (uint32_t)__bfloat16_as_ushort(hi0) |
                    ((uint32_t)__bfloat16_as_ushort(hi1) << 16);
                *(uint32_t*)(hldst + (size_t)b * H_ + jg0) =
                    (uint32_t)__bfloat16_as_ushort(lo0) |
                    ((uint32_t)__bfloat16_as_ushort(lo1) << 16);
            }

        // Per-n barrier: only the 8 CTAs sharing this n must sync.
        __threadfence();
        __syncthreads();
        if (tid == 0) {
            int target = t + 1;
            int old = atomicAdd(&g_bar_cnt[n], 1);
            if (old == 7) {
                g_bar_cnt[n] = 0;
                __threadfence();
                g_bar_gen[n] = target;
            } else {
                while (g_bar_gen[n] < target) { }
            }
        }
        __syncthreads();
    }
}

// ---------------------------------------------------------------------------
extern "C" void kernel_launch(void* const* d_in, const int* in_sizes, int n_in,
                              void* d_out, int out_size) {
    const float* x   = (const float*)d_in[0];
    const float* wih = (const float*)d_in[1];
    const float* whh = (const float*)d_in[2];
    const float* bih = (const float*)d_in[3];
    const float* bhh = (const float*)d_in[4];
    float* out = (float*)d_out;

    const int smem1 = 4 * TILE_ELE * (int)sizeof(__nv_bfloat16);       // 73,728 B
    const int smem2 = (2 * 96 * WPAD + 2 * 64 * WPAD) *
                      (int)sizeof(__nv_bfloat16);                      // 168,960 B
    cudaFuncSetAttribute(ih_mma_kernel,
                         cudaFuncAttributeMaxDynamicSharedMemorySize, smem1);
    cudaFuncSetAttribute(gru_mma_kernel,
                         cudaFuncAttributeMaxDynamicSharedMemorySize, smem2);

    zero_kernel<<<256, 256>>>();

    const size_t nx4 = (size_t)B_ * N_ * T_ * I_ / 4;
    const size_t nw4 = (size_t)N_ * G3 * I_ / 4;
    cvt_hilo_kernel<<<4096, 256>>>(x, 0, nx4);
    cvt_hilo_kernel<<<1024, 256>>>(wih, 1, nw4);

    ih_mma_kernel<<<dim3(64, 6, 16), 256, smem1>>>(bih);
    gru_mma_kernel<<<dim3(8, 16), 256, smem2>>>(whh, bhh, out);
}